// round 16
// baseline (speedup 1.0000x reference)
#include <cuda_runtime.h>
#include <cstdint>

namespace {
constexpr int L        = 512;
constexpr int C        = 128;
constexpr int F        = 128;
constexpr int Kw       = 7;
constexpr int L_OUT    = L - Kw + 1;   // 506
constexpr int KC       = Kw * C;       // 896
constexpr int BK       = 32;           // K chunk
constexpr int NCHUNK   = KC / BK;      // 28
constexpr int STAGES   = 3;
constexpr int A_STAGE_ELE = 128 * BK;  // 4096 floats (no padding; XOR swizzle)
constexpr int B_STAGE_ELE = BK * F;    // 4096 floats (no padding; XOR swizzle)
constexpr size_t SMEM_BYTES = (size_t)STAGES * (A_STAGE_ELE + B_STAGE_ELE) * 4; // 98304
constexpr int NTHREADS = 256;          // 8 warps: 4 along M x 2 along N, 32Mx64N each
}

__device__ __forceinline__ uint32_t f2tf(float f) {
    uint32_t r;
    asm("cvt.rna.tf32.f32 %0, %1;" : "=r"(r) : "f"(f));
    return r;
}

__device__ __forceinline__ void mma_tf32(float* c, const uint32_t* a, const uint32_t* b) {
    asm volatile(
        "mma.sync.aligned.m16n8k8.row.col.f32.tf32.tf32.f32 "
        "{%0,%1,%2,%3},{%4,%5,%6,%7},{%8,%9},{%0,%1,%2,%3};"
        : "+f"(c[0]), "+f"(c[1]), "+f"(c[2]), "+f"(c[3])
        : "r"(a[0]), "r"(a[1]), "r"(a[2]), "r"(a[3]), "r"(b[0]), "r"(b[1]));
}

__global__ void __launch_bounds__(NTHREADS, 2)
LocalBlock_kernel(const float* __restrict__ x, const float* __restrict__ w,
                  const float* __restrict__ bias, const float* __restrict__ gamma,
                  const float* __restrict__ beta, const float* __restrict__ mean,
                  const float* __restrict__ var, float* __restrict__ out)
{
    extern __shared__ float smem[];
    float* As = smem;                                 // [STAGES][128][32] swizzled
    float* Bs = smem + STAGES * A_STAGE_ELE;          // [STAGES][32][128] swizzled
    __shared__ float s_inv[F];
    __shared__ float s_cst[F];

    const int l   = blockIdx.x;
    const int tid = threadIdx.x;

    if (tid < F) {
        float iv = gamma[tid] * rsqrtf(var[tid] + 1e-3f);
        s_inv[tid] = iv;
        s_cst[tid] = bias[(size_t)l * F + tid] * iv + beta[tid] - mean[tid] * iv;
    }

    const float* xb = x + (size_t)l * C;              // A[b][k] = xb[b*L*C + k]
    const float* wb = w + (size_t)l * KC * F;         // B[k][f]

    const uint32_t sA = (uint32_t)__cvta_generic_to_shared(As);
    const uint32_t sB = (uint32_t)__cvta_generic_to_shared(Bs);

    auto load_stage = [&](int stage, int kc0) {
        const uint32_t sa = sA + stage * A_STAGE_ELE * 4;
        const uint32_t sb = sB + stage * B_STAGE_ELE * 4;
        // A chunk: 128 rows x 32 floats = 1024 float4 -> 4 per thread
        #pragma unroll
        for (int i = 0; i < 4; i++) {
            int idx = tid + i * NTHREADS;
            int row = idx >> 3;
            int c4  = (idx & 7) << 2;                 // k base, multiple of 4
            int sw  = c4 ^ ((row & 7) << 2);          // XOR swizzle, 16B-preserving
            const float* g = xb + (size_t)row * (L * C) + kc0 + c4;
            asm volatile("cp.async.cg.shared.global [%0], [%1], 16;"
                         :: "r"(sa + (row * BK + sw) * 4), "l"(g));
        }
        // B chunk: 32 rows x 128 floats = 1024 float4 -> 4 per thread
        #pragma unroll
        for (int i = 0; i < 4; i++) {
            int idx = tid + i * NTHREADS;
            int row = idx >> 5;
            int c4  = (idx & 31) << 2;                // f base, multiple of 4
            int sw  = c4 ^ ((row & 3) << 3);          // XOR swizzle, 16B-preserving
            const float* g = wb + (size_t)(kc0 + row) * F + c4;
            asm volatile("cp.async.cg.shared.global [%0], [%1], 16;"
                         :: "r"(sb + (row * F + sw) * 4), "l"(g));
        }
        asm volatile("cp.async.commit_group;");
    };

    // Prologue: two chunks in flight
    load_stage(0, 0);
    load_stage(1, BK);

    const int warp = tid >> 5, lane = tid & 31;
    const int wm = (warp >> 1) * 32;   // 4 warps along M
    const int wn = (warp & 1) * 64;    // 2 warps along N
    const int g4 = lane >> 2, t4 = lane & 3;

    float acc[2][8][4];
    #pragma unroll
    for (int mi = 0; mi < 2; mi++)
        #pragma unroll
        for (int ni = 0; ni < 8; ni++)
            #pragma unroll
            for (int q = 0; q < 4; q++) acc[mi][ni][q] = 0.f;

    for (int kt = 0; kt < NCHUNK; kt++) {
        asm volatile("cp.async.wait_group 1;");   // chunk kt arrived (kt+1 may be in flight)
        __syncthreads();                          // all warps done with kt-1 -> stage (kt+2)%3 free

        if (kt + 2 < NCHUNK)
            load_stage((kt + 2) % STAGES, (kt + 2) * BK);
        else
            asm volatile("cp.async.commit_group;");

        const float* As_s = As + (kt % STAGES) * A_STAGE_ELE;
        const float* Bs_s = Bs + (kt % STAGES) * B_STAGE_ELE;

        #pragma unroll
        for (int k8 = 0; k8 < BK / 8; k8++) {
            const int kb = k8 * 8;
            uint32_t a[2][4], b[8][2];
            const int oa = (kb + t4) ^ (g4 << 2);     // A swizzled k-offset (bit2 of kb+t4 is 0)
            #pragma unroll
            for (int mi = 0; mi < 2; mi++) {
                const float* ap = As_s + (wm + mi * 16 + g4) * BK;
                a[mi][0] = f2tf(ap[oa]);
                a[mi][1] = f2tf(ap[8 * BK + oa]);
                a[mi][2] = f2tf(ap[oa ^ 4]);
                a[mi][3] = f2tf(ap[8 * BK + (oa ^ 4)]);
            }
            const float* bp0 = Bs_s + (kb + t4) * F;
            const int swb = t4 << 3;                  // (kb+t4)&3 == t4
            #pragma unroll
            for (int ni = 0; ni < 8; ni++) {
                const int f = (wn + ni * 8 + g4) ^ swb;
                b[ni][0] = f2tf(bp0[f]);
                b[ni][1] = f2tf(bp0[4 * F + f]);
            }
            #pragma unroll
            for (int mi = 0; mi < 2; mi++)
                #pragma unroll
                for (int ni = 0; ni < 8; ni++)
                    mma_tf32(acc[mi][ni], a[mi], b[ni]);
        }
    }

    // Epilogue: BN affine + ReLU, write out[b][l][f]
    #pragma unroll
    for (int mi = 0; mi < 2; mi++) {
        const int r0 = wm + mi * 16 + g4;
        #pragma unroll
        for (int ni = 0; ni < 8; ni++) {
            const int col = wn + ni * 8 + t4 * 2;
            const float i0 = s_inv[col], i1 = s_inv[col + 1];
            const float k0 = s_cst[col], k1 = s_cst[col + 1];
            float v0 = fmaxf(fmaf(acc[mi][ni][0], i0, k0), 0.f);
            float v1 = fmaxf(fmaf(acc[mi][ni][1], i1, k1), 0.f);
            float v2 = fmaxf(fmaf(acc[mi][ni][2], i0, k0), 0.f);
            float v3 = fmaxf(fmaf(acc[mi][ni][3], i1, k1), 0.f);
            float2* o0 = (float2*)(out + (size_t)r0 * (L_OUT * F) + (size_t)l * F + col);
            float2* o1 = (float2*)(out + (size_t)(r0 + 8) * (L_OUT * F) + (size_t)l * F + col);
            *o0 = make_float2(v0, v1);
            *o1 = make_float2(v2, v3);
        }
    }
}

extern "C" void kernel_launch(void* const* d_in, const int* in_sizes, int n_in,
                              void* d_out, int out_size)
{
    (void)in_sizes; (void)n_in; (void)out_size;
    const float* x     = (const float*)d_in[0];
    const float* w     = (const float*)d_in[1];
    const float* bias  = (const float*)d_in[2];
    const float* gamma = (const float*)d_in[3];
    const float* beta  = (const float*)d_in[4];
    const float* mean  = (const float*)d_in[5];
    const float* var   = (const float*)d_in[6];
    float* out = (float*)d_out;

    cudaFuncSetAttribute(LocalBlock_kernel,
                         cudaFuncAttributeMaxDynamicSharedMemorySize,
                         (int)SMEM_BYTES);
    LocalBlock_kernel<<<L_OUT, NTHREADS, SMEM_BYTES>>>(x, w, bias, gamma, beta, mean, var, out);
}

// round 17
// speedup vs baseline: 1.1261x; 1.1261x over previous
#include <cuda_runtime.h>
#include <cstdint>

namespace {
constexpr int L        = 512;
constexpr int C        = 128;
constexpr int F        = 128;
constexpr int Kw       = 7;
constexpr int L_OUT    = L - Kw + 1;   // 506
constexpr int KC       = Kw * C;       // 896
constexpr int BK       = 32;           // K chunk
constexpr int NCHUNK   = KC / BK;      // 28
constexpr int STAGES   = 3;
constexpr int A_STAGE_ELE = 128 * BK;  // 4096 floats (no padding; XOR swizzle)
constexpr int B_STAGE_ELE = BK * F;    // 4096 floats (no padding; XOR swizzle)
constexpr size_t SMEM_BYTES = (size_t)STAGES * (A_STAGE_ELE + B_STAGE_ELE) * 4; // 98304
constexpr int NTHREADS = 256;          // 8 warps: 4 along M x 2 along N, 32Mx64N each
}

__device__ __forceinline__ uint32_t f2tf(float f) {
    uint32_t r;
    asm("cvt.rna.tf32.f32 %0, %1;" : "=r"(r) : "f"(f));
    return r;
}

__device__ __forceinline__ void mma_tf32(float* c, const uint32_t* a, const uint32_t* b) {
    asm volatile(
        "mma.sync.aligned.m16n8k8.row.col.f32.tf32.tf32.f32 "
        "{%0,%1,%2,%3},{%4,%5,%6,%7},{%8,%9},{%0,%1,%2,%3};"
        : "+f"(c[0]), "+f"(c[1]), "+f"(c[2]), "+f"(c[3])
        : "r"(a[0]), "r"(a[1]), "r"(a[2]), "r"(a[3]), "r"(b[0]), "r"(b[1]));
}

__global__ void __launch_bounds__(NTHREADS, 2)
LocalBlock_kernel(const float* __restrict__ x, const float* __restrict__ w,
                  const float* __restrict__ bias, const float* __restrict__ gamma,
                  const float* __restrict__ beta, const float* __restrict__ mean,
                  const float* __restrict__ var, float* __restrict__ out)
{
    extern __shared__ float smem[];
    float* As = smem;                                 // [STAGES][128][32] swizzled
    float* Bs = smem + STAGES * A_STAGE_ELE;          // [STAGES][32][128] swizzled
    __shared__ float s_inv[F];
    __shared__ float s_cst[F];

    const int l   = blockIdx.x;
    const int tid = threadIdx.x;

    if (tid < F) {
        float iv = gamma[tid] * rsqrtf(var[tid] + 1e-3f);
        s_inv[tid] = iv;
        s_cst[tid] = bias[(size_t)l * F + tid] * iv + beta[tid] - mean[tid] * iv;
    }

    const float* xb = x + (size_t)l * C;              // A[b][k] = xb[b*L*C + k]
    const float* wb = w + (size_t)l * KC * F;         // B[k][f]

    const uint32_t sA = (uint32_t)__cvta_generic_to_shared(As);
    const uint32_t sB = (uint32_t)__cvta_generic_to_shared(Bs);

    auto load_stage = [&](int stage, int kc0) {
        const uint32_t sa = sA + stage * A_STAGE_ELE * 4;
        const uint32_t sb = sB + stage * B_STAGE_ELE * 4;
        // A chunk: 128 rows x 32 floats = 1024 float4 -> 4 per thread
        #pragma unroll
        for (int i = 0; i < 4; i++) {
            int idx = tid + i * NTHREADS;
            int row = idx >> 3;
            int c4  = (idx & 7) << 2;                 // k base, multiple of 4
            int sw  = c4 ^ ((row & 7) << 2);          // XOR swizzle, 16B-preserving
            const float* g = xb + (size_t)row * (L * C) + kc0 + c4;
            asm volatile("cp.async.cg.shared.global [%0], [%1], 16;"
                         :: "r"(sa + (row * BK + sw) * 4), "l"(g));
        }
        // B chunk: 32 rows x 128 floats = 1024 float4 -> 4 per thread
        #pragma unroll
        for (int i = 0; i < 4; i++) {
            int idx = tid + i * NTHREADS;
            int row = idx >> 5;
            int c4  = (idx & 31) << 2;                // f base, multiple of 4
            int sw  = c4 ^ ((row & 3) << 3);          // XOR swizzle, 16B-preserving
            const float* g = wb + (size_t)(kc0 + row) * F + c4;
            asm volatile("cp.async.cg.shared.global [%0], [%1], 16;"
                         :: "r"(sb + (row * F + sw) * 4), "l"(g));
        }
        asm volatile("cp.async.commit_group;");
    };

    // Prologue: two chunks in flight
    load_stage(0, 0);
    load_stage(1, BK);

    const int warp = tid >> 5, lane = tid & 31;
    const int wm = (warp >> 1) * 32;   // 4 warps along M
    const int wn = (warp & 1) * 64;    // 2 warps along N
    const int g4 = lane >> 2, t4 = lane & 3;

    // ldmatrix per-lane row geometry: tile t = lane>>3, row r = lane&7
    const int lt = lane >> 3, lr = lane & 7;
    const int m_ld0 = wm + ((lt & 1) << 3) + lr;      // row for mi=0 (add 16 for mi=1)
    const int kgrp_t = lt >> 1;                        // k-group offset from tile

    float acc[2][8][4];
    #pragma unroll
    for (int mi = 0; mi < 2; mi++)
        #pragma unroll
        for (int ni = 0; ni < 8; ni++)
            #pragma unroll
            for (int q = 0; q < 4; q++) acc[mi][ni][q] = 0.f;

    const int kstart = warp & 3;                       // phase stagger per warp

    for (int kt = 0; kt < NCHUNK; kt++) {
        asm volatile("cp.async.wait_group 1;");   // chunk kt arrived (kt+1 may be in flight)
        __syncthreads();                          // all warps done with kt-1 -> stage (kt+2)%3 free

        if (kt + 2 < NCHUNK)
            load_stage((kt + 2) % STAGES, (kt + 2) * BK);
        else
            asm volatile("cp.async.commit_group;");

        const uint32_t As_u = sA + (kt % STAGES) * A_STAGE_ELE * 4;
        const float* Bs_s = Bs + (kt % STAGES) * B_STAGE_ELE;

        #pragma unroll
        for (int kk = 0; kk < BK / 8; kk++) {
            const int k8 = (kk + kstart) & 3;          // staggered k-step order
            const int kb = k8 * 8;
            uint32_t a[2][4], b[8][2];
            // A fragments via ldmatrix.x4 (one per mi)
            #pragma unroll
            for (int mi = 0; mi < 2; mi++) {
                const int m = m_ld0 + mi * 16;
                const uint32_t addr =
                    As_u + (uint32_t)(m * 128) +
                    (uint32_t)(((k8 * 2 + kgrp_t) ^ (m & 7)) << 4);
                asm volatile(
                    "ldmatrix.sync.aligned.m8n8.x4.shared.b16 {%0,%1,%2,%3}, [%4];"
                    : "=r"(a[mi][0]), "=r"(a[mi][1]), "=r"(a[mi][2]), "=r"(a[mi][3])
                    : "r"(addr));
                a[mi][0] = f2tf(__uint_as_float(a[mi][0]));
                a[mi][1] = f2tf(__uint_as_float(a[mi][1]));
                a[mi][2] = f2tf(__uint_as_float(a[mi][2]));
                a[mi][3] = f2tf(__uint_as_float(a[mi][3]));
            }
            // B fragments: raw f32 bits (HW tf32 truncation; coherent bias ~2.4e-4)
            const float* bp0 = Bs_s + (kb + t4) * F;
            const int swb = t4 << 3;                   // (kb+t4)&3 == t4
            #pragma unroll
            for (int ni = 0; ni < 8; ni++) {
                const int f = (wn + ni * 8 + g4) ^ swb;
                b[ni][0] = __float_as_uint(bp0[f]);
                b[ni][1] = __float_as_uint(bp0[4 * F + f]);
            }
            #pragma unroll
            for (int mi = 0; mi < 2; mi++)
                #pragma unroll
                for (int ni = 0; ni < 8; ni++)
                    mma_tf32(acc[mi][ni], a[mi], b[ni]);
        }
    }

    // Epilogue: BN affine + ReLU, write out[b][l][f]
    #pragma unroll
    for (int mi = 0; mi < 2; mi++) {
        const int r0 = wm + mi * 16 + g4;
        #pragma unroll
        for (int ni = 0; ni < 8; ni++) {
            const int col = wn + ni * 8 + t4 * 2;
            const float i0 = s_inv[col], i1 = s_inv[col + 1];
            const float k0 = s_cst[col], k1 = s_cst[col + 1];
            float v0 = fmaxf(fmaf(acc[mi][ni][0], i0, k0), 0.f);
            float v1 = fmaxf(fmaf(acc[mi][ni][1], i1, k1), 0.f);
            float v2 = fmaxf(fmaf(acc[mi][ni][2], i0, k0), 0.f);
            float v3 = fmaxf(fmaf(acc[mi][ni][3], i1, k1), 0.f);
            float2* o0 = (float2*)(out + (size_t)r0 * (L_OUT * F) + (size_t)l * F + col);
            float2* o1 = (float2*)(out + (size_t)(r0 + 8) * (L_OUT * F) + (size_t)l * F + col);
            *o0 = make_float2(v0, v1);
            *o1 = make_float2(v2, v3);
        }
    }
}

extern "C" void kernel_launch(void* const* d_in, const int* in_sizes, int n_in,
                              void* d_out, int out_size)
{
    (void)in_sizes; (void)n_in; (void)out_size;
    const float* x     = (const float*)d_in[0];
    const float* w     = (const float*)d_in[1];
    const float* bias  = (const float*)d_in[2];
    const float* gamma = (const float*)d_in[3];
    const float* beta  = (const float*)d_in[4];
    const float* mean  = (const float*)d_in[5];
    const float* var   = (const float*)d_in[6];
    float* out = (float*)d_out;

    cudaFuncSetAttribute(LocalBlock_kernel,
                         cudaFuncAttributeMaxDynamicSharedMemorySize,
                         (int)SMEM_BYTES);
    LocalBlock_kernel<<<L_OUT, NTHREADS, SMEM_BYTES>>>(x, w, bias, gamma, beta, mean, var, out);
}